// round 7
// baseline (speedup 1.0000x reference)
#include <cuda_runtime.h>
#include <math.h>

#define N_NODES 50000
#define N_EDGES 1600000
#define HID 32
#define HOR 12

// ---------------- scratch (static device allocation) ----------------
__device__ float g_deg[N_NODES];
__device__ float g_dinv[N_NODES];
__device__ float4 g_Xs4[N_NODES * 8];    // dinv[s] * x[s]
__device__ float4 g_h0s4[N_NODES * 8];   // dinv[s] * h0[s]
__device__ float g_LX[N_NODES * HID];    // T = sum w * Xs   (scaled by -dinv[d] in gates)
__device__ float g_Lh[N_NODES * HID];
__device__ int   g_hflag;                // any(h0 != 0)

// ---------------- deg = segment_sum(w, src); fused h0!=0 probe; 4 edges/thread ----------------
__global__ void __launch_bounds__(256) k_deg(
        const int4* __restrict__ src4,
        const float4* __restrict__ w4,
        const float4* __restrict__ h04) {
    int i = blockIdx.x * blockDim.x + threadIdx.x;     // 400000 threads
    if (i < N_EDGES / 4) {
        int4   s = src4[i];
        float4 w = w4[i];
        if ((unsigned)s.x < N_NODES) atomicAdd(&g_deg[s.x], w.x);
        if ((unsigned)s.y < N_NODES) atomicAdd(&g_deg[s.y], w.y);
        if ((unsigned)s.z < N_NODES) atomicAdd(&g_deg[s.z], w.z);
        if ((unsigned)s.w < N_NODES) atomicAdd(&g_deg[s.w], w.w);
    }
    if (i < N_NODES * HID / 4) {
        float4 v = h04[i];
        if (v.x != 0.f || v.y != 0.f || v.z != 0.f || v.w != 0.f) g_hflag = 1;
    }
}

// ---------------- dinv + pre-scale Xs = dinv*x (and h0s if hf) ----------------
__global__ void __launch_bounds__(256) k_xs(
        const float4* __restrict__ x4,
        const float4* __restrict__ h04) {
    int i = blockIdx.x * blockDim.x + threadIdx.x;     // N_NODES*8 float4s
    if (i < N_NODES * 8) {
        int node = i >> 3;
        float d = g_deg[node];
        float di = d > 0.f ? rsqrtf(d) : 0.f;
        if ((i & 7) == 0) g_dinv[node] = di;
        float4 v = x4[i];
        v.x *= di; v.y *= di; v.z *= di; v.w *= di;
        g_Xs4[i] = v;
        if (g_hflag) {
            float4 h = h04[i];
            h.x *= di; h.y *= di; h.z *= di; h.w *= di;
            g_h0s4[i] = h;
        }
    }
}

// ---------------- edge aggregation: T[dst] += w * Xs[src], vectorized RED.128 ----------------
// warp = 32 edges. sub=lane>>3 picks edge within group-of-4, q=lane&7 feature quad.
__global__ void __launch_bounds__(256) k_edge(
        const int* __restrict__ src,
        const int* __restrict__ dst,
        const float* __restrict__ w) {
    int lane = threadIdx.x & 31;
    long long wid = (long long)(blockIdx.x * blockDim.x + threadIdx.x) >> 5;
    long long e = wid * 32 + lane;

    int s = 0, d = 0;
    float nv = 0.f;
    if (e < N_EDGES) {
        int ss = src[e];
        int dd = dst[e];
        if ((unsigned)ss < N_NODES && (unsigned)dd < N_NODES) {
            s = ss; d = dd; nv = w[e];
        }
    }
    int hf = g_hflag;
    int sub = lane >> 3;     // edge-in-group 0..3
    int q   = lane & 7;      // feature quad 0..7
    const float4* xs  = g_Xs4;
    const float4* h0s = g_h0s4;

    #pragma unroll
    for (int it = 0; it < 8; it++) {
        int srcLane = it * 4 + sub;
        int   si  = __shfl_sync(0xffffffffu, s, srcLane);
        int   di  = __shfl_sync(0xffffffffu, d, srcLane);
        float nvi = __shfl_sync(0xffffffffu, nv, srcLane);
        if (nvi != 0.f) {
            float4 xv = __ldg(&xs[(size_t)si * 8 + q]);
            asm volatile("red.global.add.v4.f32 [%0], {%1,%2,%3,%4};"
                         :: "l"(&g_LX[di * HID + q * 4]),
                            "f"(nvi * xv.x), "f"(nvi * xv.y),
                            "f"(nvi * xv.z), "f"(nvi * xv.w)
                         : "memory");
            if (hf) {
                float4 hv = __ldg(&h0s[(size_t)si * 8 + q]);
                asm volatile("red.global.add.v4.f32 [%0], {%1,%2,%3,%4};"
                             :: "l"(&g_Lh[di * HID + q * 4]),
                                "f"(nvi * hv.x), "f"(nvi * hv.y),
                                "f"(nvi * hv.z), "f"(nvi * hv.w)
                             : "memory");
            }
        }
    }
}

// ---------------- gates + LSTM cell + head; persistent blocks, Wx loaded once ----------------
#define GBLOCKS 592
__global__ void __launch_bounds__(256) k_gates(
        const float4* __restrict__ x4,
        const float4* __restrict__ h04,
        const float* __restrict__ c0,
        const float* __restrict__ Wx,   // [4][2][32][32]
        const float* __restrict__ bx,
        const float* __restrict__ Wh,
        const float* __restrict__ bh,
        const float* __restrict__ wc,
        const float* __restrict__ b,
        const float* __restrict__ Wl,   // [32][12]
        const float* __restrict__ bl,
        float* __restrict__ out) {
    __shared__ float sWx[8192];          // 32 KB
    __shared__ float sU[32 * 2 * 32];    // 8 KB
    __shared__ float sWl[HID * HOR];
    __shared__ float sbsum[4 * HID];
    __shared__ float swc[3 * HID];
    __shared__ float sbl[HOR];

    int tid = threadIdx.x;
    int hf = g_hflag;

    for (int i = tid; i < 8192; i += 256) sWx[i] = Wx[i];
    for (int i = tid; i < HID * HOR; i += 256) sWl[i] = Wl[i];
    if (tid < 4 * HID) sbsum[tid] = bx[tid] + bh[tid] + b[tid];
    if (tid < 3 * HID) swc[tid] = wc[tid];
    if (tid < HOR)     sbl[tid] = bl[tid];

    const float4* lx4 = (const float4*)g_LX;
    const float4* lh4 = (const float4*)g_Lh;

    int npt = hf ? 16 : 32;
    int ntiles = (N_NODES + npt - 1) / npt;
    int warp = tid >> 5;
    int j = tid & 31;
    int npw = npt >> 3;

    float* oh = out;
    float* oH = out + (size_t)N_NODES * HOR;
    float* oC = oH + (size_t)N_NODES * HID;

    for (int tile = blockIdx.x; tile < ntiles; tile += GBLOCKS) {
        int nodeBase = tile * npt;
        __syncthreads();
        if (!hf) {
            for (int i = tid; i < 512; i += 256) {
                int n = i >> 4, m = (i >> 3) & 1, kq = i & 7;
                int node = nodeBase + n;
                float4 v = make_float4(0.f, 0.f, 0.f, 0.f);
                if (node < N_NODES) {
                    if (m) {
                        v = lx4[node * 8 + kq];
                        float sc = -g_dinv[node];
                        v.x *= sc; v.y *= sc; v.z *= sc; v.w *= sc;
                    } else {
                        v = x4[node * 8 + kq];
                    }
                }
                ((float4*)sU)[(n * 2 + m) * 8 + kq] = v;
            }
        } else {
            for (int i = tid; i < 512; i += 256) {
                int n = i >> 5, m = (i >> 3) & 3, kq = i & 7;
                int node = nodeBase + n;
                float4 v = make_float4(0.f, 0.f, 0.f, 0.f);
                if (node < N_NODES) {
                    if (m == 0) v = x4[node * 8 + kq];
                    else if (m == 2) v = h04[node * 8 + kq];
                    else {
                        v = (m == 1) ? lx4[node * 8 + kq] : lh4[node * 8 + kq];
                        float sc = -g_dinv[node];
                        v.x *= sc; v.y *= sc; v.z *= sc; v.w *= sc;
                    }
                }
                ((float4*)sU)[(n * 4 + m) * 8 + kq] = v;
            }
        }
        __syncthreads();

        float acc[4][4];
        #pragma unroll
        for (int n = 0; n < 4; n++)
            #pragma unroll
            for (int g = 0; g < 4; g++) acc[n][g] = 0.f;

        int nb = warp * npw;
        if (!hf) {
            #pragma unroll
            for (int k = 0; k < 32; k++) {
                float wa[4], wb[4];
                #pragma unroll
                for (int g = 0; g < 4; g++) {
                    wa[g] = sWx[g * 2048 +        k * 32 + j];
                    wb[g] = sWx[g * 2048 + 1024 + k * 32 + j];
                }
                #pragma unroll
                for (int n = 0; n < 4; n++) {
                    float xv  = sU[((nb + n) * 2 + 0) * 32 + k];
                    float lxv = sU[((nb + n) * 2 + 1) * 32 + k];
                    #pragma unroll
                    for (int g = 0; g < 4; g++)
                        acc[n][g] += xv * wa[g] + lxv * wb[g];
                }
            }
        } else {
            #pragma unroll
            for (int k = 0; k < 32; k++) {
                float wa[4], wb[4], wha[4], whb[4];
                #pragma unroll
                for (int g = 0; g < 4; g++) {
                    wa[g]  = sWx[g * 2048 +        k * 32 + j];
                    wb[g]  = sWx[g * 2048 + 1024 + k * 32 + j];
                    wha[g] = __ldg(&Wh[g * 2048 +        k * 32 + j]);
                    whb[g] = __ldg(&Wh[g * 2048 + 1024 + k * 32 + j]);
                }
                #pragma unroll
                for (int n = 0; n < 2; n++) {
                    float xv  = sU[((nb + n) * 4 + 0) * 32 + k];
                    float lxv = sU[((nb + n) * 4 + 1) * 32 + k];
                    float hv  = sU[((nb + n) * 4 + 2) * 32 + k];
                    float lhv = sU[((nb + n) * 4 + 3) * 32 + k];
                    #pragma unroll
                    for (int g = 0; g < 4; g++)
                        acc[n][g] += xv * wa[g] + lxv * wb[g] + hv * wha[g] + lhv * whb[g];
                }
            }
        }

        #pragma unroll
        for (int n = 0; n < 4; n++) {
            if (n >= npw) break;
            int node = nodeBase + nb + n;
            if (node < N_NODES) {
                float c0v = c0[node * HID + j];
                float preI = acc[n][0] + sbsum[0 * 32 + j] + swc[0 * 32 + j] * c0v;
                float preF = acc[n][1] + sbsum[1 * 32 + j] + swc[1 * 32 + j] * c0v;
                float preT = acc[n][2] + sbsum[2 * 32 + j];
                float I  = 1.f / (1.f + __expf(-preI));
                float Fg = 1.f / (1.f + __expf(-preF));
                float T  = tanhf(preT);
                float C  = Fg * c0v + I * T;
                float preO = acc[n][3] + sbsum[3 * 32 + j] + swc[2 * 32 + j] * C;
                float O  = 1.f / (1.f + __expf(-preO));
                float H  = O * tanhf(C);

                oH[node * HID + j] = H;
                oC[node * HID + j] = C;

                float rH = fmaxf(H, 0.f);
                float keep = 0.f;
                #pragma unroll
                for (int k = 0; k < 32; k++) {
                    float rHk = __shfl_sync(0xffffffffu, rH, k);
                    if (j < HOR) keep += rHk * sWl[k * HOR + j];
                }
                if (j < HOR) oh[node * HOR + j] = keep + sbl[j];
            }
        }
    }
}

// ---------------- launch ----------------
extern "C" void kernel_launch(void* const* d_in, const int* in_sizes, int n_in,
                              void* d_out, int out_size) {
    int iX, iEI, iEW, iWx, iBx, iWh, iBh, iWc, iB, iWl, iBl, iH0, iC0;
    if (n_in > 8 && in_sizes[8] == 2 * N_EDGES) {
        iWl = 0; iWh = 1; iWx = 2; iB = 3; iBl = 4; iBh = 5; iBx = 6;
        iC0 = 7; iEI = 8; iEW = 9; iH0 = 10; iWc = 11; iX = 12;
    } else {
        iX = 0; iEI = 1; iEW = 2; iWx = 3; iBx = 4; iWh = 5; iBh = 6;
        iWc = 7; iB = 8; iWl = 9; iBl = 10; iH0 = 11; iC0 = 12;
    }

    const float* x    = (const float*)d_in[iX];
    const int*   ei   = (const int*)d_in[iEI];     // int32 (JAX x64 off)
    const float* ew   = (const float*)d_in[iEW];
    const float* Wx   = (const float*)d_in[iWx];
    const float* bx   = (const float*)d_in[iBx];
    const float* Wh   = (const float*)d_in[iWh];
    const float* bh   = (const float*)d_in[iBh];
    const float* wc   = (const float*)d_in[iWc];
    const float* b    = (const float*)d_in[iB];
    const float* Wl   = (const float*)d_in[iWl];
    const float* bl   = (const float*)d_in[iBl];
    const float* h0   = (const float*)d_in[iH0];
    const float* c0   = (const float*)d_in[iC0];
    float*       out  = (float*)d_out;

    const int* src = ei;
    const int* dst = ei + N_EDGES;

    void *pDeg, *pLX, *pLh, *pFlag;
    cudaGetSymbolAddress(&pDeg,  g_deg);
    cudaGetSymbolAddress(&pLX,   g_LX);
    cudaGetSymbolAddress(&pLh,   g_Lh);
    cudaGetSymbolAddress(&pFlag, g_hflag);
    cudaMemsetAsync(pDeg,  0, N_NODES * sizeof(float));
    cudaMemsetAsync(pLX,   0, N_NODES * HID * sizeof(float));
    cudaMemsetAsync(pLh,   0, N_NODES * HID * sizeof(float));
    cudaMemsetAsync(pFlag, 0, sizeof(int));

    k_deg<<<(N_NODES * HID / 4 + 255) / 256, 256>>>(
        (const int4*)src, (const float4*)ew, (const float4*)h0);

    k_xs<<<(N_NODES * 8 + 255) / 256, 256>>>(
        (const float4*)x, (const float4*)h0);

    long long warps = (N_EDGES + 31) / 32;
    k_edge<<<(int)((warps * 32 + 255) / 256), 256>>>(src, dst, ew);

    k_gates<<<GBLOCKS, 256>>>((const float4*)x, (const float4*)h0, c0,
                              Wx, bx, Wh, bh, wc, b, Wl, bl, out);
}

// round 8
// speedup vs baseline: 1.0052x; 1.0052x over previous
#include <cuda_runtime.h>
#include <math.h>

#define N_NODES 50000
#define N_EDGES 1600000
#define HID 32
#define HOR 12

// ---------------- scratch (static device allocation) ----------------
__device__ float g_deg[N_NODES];
__device__ float g_dinv[N_NODES];
__device__ float4 g_Xs4[N_NODES * 8];    // dinv[s] * x[s]
__device__ float4 g_h0s4[N_NODES * 8];   // dinv[s] * h0[s]
__device__ float g_LX[N_NODES * HID];    // T = sum w * Xs   (scaled by -dinv[d] in gates)
__device__ float g_Lh[N_NODES * HID];
__device__ int   g_hflag;                // any(h0 != 0)

// ---------------- deg = segment_sum(w, src); fused h0!=0 probe; 4 edges/thread ----------------
__global__ void __launch_bounds__(256) k_deg(
        const int4* __restrict__ src4,
        const float4* __restrict__ w4,
        const float4* __restrict__ h04) {
    int i = blockIdx.x * blockDim.x + threadIdx.x;
    if (i < N_EDGES / 4) {
        int4   s = src4[i];
        float4 w = w4[i];
        if ((unsigned)s.x < N_NODES) atomicAdd(&g_deg[s.x], w.x);
        if ((unsigned)s.y < N_NODES) atomicAdd(&g_deg[s.y], w.y);
        if ((unsigned)s.z < N_NODES) atomicAdd(&g_deg[s.z], w.z);
        if ((unsigned)s.w < N_NODES) atomicAdd(&g_deg[s.w], w.w);
    }
    if (i < N_NODES * HID / 4) {
        float4 v = h04[i];
        if (v.x != 0.f || v.y != 0.f || v.z != 0.f || v.w != 0.f) g_hflag = 1;
    }
}

// ---------------- dinv + pre-scale Xs = dinv*x (and h0s if hf) ----------------
__global__ void __launch_bounds__(256) k_xs(
        const float4* __restrict__ x4,
        const float4* __restrict__ h04) {
    int i = blockIdx.x * blockDim.x + threadIdx.x;
    if (i < N_NODES * 8) {
        int node = i >> 3;
        float d = g_deg[node];
        float di = d > 0.f ? rsqrtf(d) : 0.f;
        if ((i & 7) == 0) g_dinv[node] = di;
        float4 v = x4[i];
        v.x *= di; v.y *= di; v.z *= di; v.w *= di;
        g_Xs4[i] = v;
        if (g_hflag) {
            float4 h = h04[i];
            h.x *= di; h.y *= di; h.z *= di; h.w *= di;
            g_h0s4[i] = h;
        }
    }
}

// ---------------- edge aggregation: T[dst] += w * Xs[src], vectorized RED.128 ----------------
__global__ void __launch_bounds__(256) k_edge(
        const int* __restrict__ src,
        const int* __restrict__ dst,
        const float* __restrict__ w) {
    int lane = threadIdx.x & 31;
    long long wid = (long long)(blockIdx.x * blockDim.x + threadIdx.x) >> 5;
    long long e = wid * 32 + lane;

    int s = 0, d = 0;
    float nv = 0.f;
    if (e < N_EDGES) {
        int ss = src[e];
        int dd = dst[e];
        if ((unsigned)ss < N_NODES && (unsigned)dd < N_NODES) {
            s = ss; d = dd; nv = w[e];
        }
    }
    int hf = g_hflag;
    int sub = lane >> 3;
    int q   = lane & 7;
    const float4* xs  = g_Xs4;
    const float4* h0s = g_h0s4;

    #pragma unroll
    for (int it = 0; it < 8; it++) {
        int srcLane = it * 4 + sub;
        int   si  = __shfl_sync(0xffffffffu, s, srcLane);
        int   di  = __shfl_sync(0xffffffffu, d, srcLane);
        float nvi = __shfl_sync(0xffffffffu, nv, srcLane);
        if (nvi != 0.f) {
            float4 xv = __ldg(&xs[(size_t)si * 8 + q]);
            asm volatile("red.global.add.v4.f32 [%0], {%1,%2,%3,%4};"
                         :: "l"(&g_LX[di * HID + q * 4]),
                            "f"(nvi * xv.x), "f"(nvi * xv.y),
                            "f"(nvi * xv.z), "f"(nvi * xv.w)
                         : "memory");
            if (hf) {
                float4 hv = __ldg(&h0s[(size_t)si * 8 + q]);
                asm volatile("red.global.add.v4.f32 [%0], {%1,%2,%3,%4};"
                             :: "l"(&g_Lh[di * HID + q * 4]),
                                "f"(nvi * hv.x), "f"(nvi * hv.y),
                                "f"(nvi * hv.z), "f"(nvi * hv.w)
                             : "memory");
            }
        }
    }
}

// ================= FAST gates kernel: only runs when h0 == 0 =================
// 48 nodes/block (6 per warp), direct grid. smem = 47.5 KB.
#define TN 48
__global__ void __launch_bounds__(256) k_gates_fast(
        const float4* __restrict__ x4,
        const float* __restrict__ c0,
        const float* __restrict__ Wx,   // [4][2][32][32]
        const float* __restrict__ bx,
        const float* __restrict__ bh,
        const float* __restrict__ wc,
        const float* __restrict__ b,
        const float* __restrict__ Wl,   // [32][12]
        const float* __restrict__ bl,
        float* __restrict__ out) {
    if (g_hflag) return;

    __shared__ float sWx[8192];          // 32 KB
    __shared__ float sU[TN * 64];        // 12 KB: [node][m][k]
    __shared__ float sWl[HID * HOR];
    __shared__ float sbsum[4 * HID];
    __shared__ float swc[3 * HID];
    __shared__ float sbl[HOR];

    int tid = threadIdx.x;
    int nodeBase = blockIdx.x * TN;

    for (int i = tid; i < 8192; i += 256) sWx[i] = Wx[i];
    for (int i = tid; i < HID * HOR; i += 256) sWl[i] = Wl[i];
    if (tid < 4 * HID) sbsum[tid] = bx[tid] + bh[tid] + b[tid];
    if (tid < 3 * HID) swc[tid] = wc[tid];
    if (tid < HOR)     sbl[tid] = bl[tid];

    const float4* lx4 = (const float4*)g_LX;

    // stage U: 768 float4
    for (int i = tid; i < TN * 16; i += 256) {
        int n = i >> 4, m = (i >> 3) & 1, kq = i & 7;
        int node = nodeBase + n;
        float4 v = make_float4(0.f, 0.f, 0.f, 0.f);
        if (node < N_NODES) {
            if (m) {
                v = lx4[node * 8 + kq];
                float sc = -g_dinv[node];
                v.x *= sc; v.y *= sc; v.z *= sc; v.w *= sc;
            } else {
                v = x4[node * 8 + kq];
            }
        }
        ((float4*)sU)[(n * 2 + m) * 8 + kq] = v;
    }
    __syncthreads();

    int warp = tid >> 5;
    int j = tid & 31;
    int nb = warp * 6;

    float acc[6][4];
    #pragma unroll
    for (int n = 0; n < 6; n++)
        #pragma unroll
        for (int g = 0; g < 4; g++) acc[n][g] = 0.f;

    #pragma unroll
    for (int k = 0; k < 32; k++) {
        float wa[4], wb[4];
        #pragma unroll
        for (int g = 0; g < 4; g++) {
            wa[g] = sWx[g * 2048 +        k * 32 + j];
            wb[g] = sWx[g * 2048 + 1024 + k * 32 + j];
        }
        #pragma unroll
        for (int n = 0; n < 6; n++) {
            float xv  = sU[(nb + n) * 64 + k];        // broadcast
            float lxv = sU[(nb + n) * 64 + 32 + k];   // broadcast
            #pragma unroll
            for (int g = 0; g < 4; g++)
                acc[n][g] += xv * wa[g] + lxv * wb[g];
        }
    }

    float* oh = out;
    float* oH = out + (size_t)N_NODES * HOR;
    float* oC = oH + (size_t)N_NODES * HID;

    #pragma unroll
    for (int n = 0; n < 6; n++) {
        int node = nodeBase + nb + n;
        if (node < N_NODES) {
            float c0v = c0[node * HID + j];
            float preI = acc[n][0] + sbsum[0 * 32 + j] + swc[0 * 32 + j] * c0v;
            float preF = acc[n][1] + sbsum[1 * 32 + j] + swc[1 * 32 + j] * c0v;
            float preT = acc[n][2] + sbsum[2 * 32 + j];
            float I  = 1.f / (1.f + __expf(-preI));
            float Fg = 1.f / (1.f + __expf(-preF));
            float T  = tanhf(preT);
            float C  = Fg * c0v + I * T;
            float preO = acc[n][3] + sbsum[3 * 32 + j] + swc[2 * 32 + j] * C;
            float O  = 1.f / (1.f + __expf(-preO));
            float H  = O * tanhf(C);

            oH[node * HID + j] = H;
            oC[node * HID + j] = C;

            float rH = fmaxf(H, 0.f);
            float keep = 0.f;
            #pragma unroll
            for (int k = 0; k < 32; k++) {
                float rHk = __shfl_sync(0xffffffffu, rH, k);
                if (j < HOR) keep += rHk * sWl[k * HOR + j];
            }
            if (j < HOR) oh[node * HOR + j] = keep + sbl[j];
        }
    }
}

// ================= GENERIC gates kernel: only runs when h0 != 0 =================
#define GBLOCKS 592
__global__ void __launch_bounds__(256) k_gates_hf(
        const float4* __restrict__ x4,
        const float4* __restrict__ h04,
        const float* __restrict__ c0,
        const float* __restrict__ Wx,
        const float* __restrict__ bx,
        const float* __restrict__ Wh,
        const float* __restrict__ bh,
        const float* __restrict__ wc,
        const float* __restrict__ b,
        const float* __restrict__ Wl,
        const float* __restrict__ bl,
        float* __restrict__ out) {
    if (!g_hflag) return;

    __shared__ float sWx[8192];
    __shared__ float sU[16 * 4 * 32];
    __shared__ float sWl[HID * HOR];
    __shared__ float sbsum[4 * HID];
    __shared__ float swc[3 * HID];
    __shared__ float sbl[HOR];

    int tid = threadIdx.x;

    for (int i = tid; i < 8192; i += 256) sWx[i] = Wx[i];
    for (int i = tid; i < HID * HOR; i += 256) sWl[i] = Wl[i];
    if (tid < 4 * HID) sbsum[tid] = bx[tid] + bh[tid] + b[tid];
    if (tid < 3 * HID) swc[tid] = wc[tid];
    if (tid < HOR)     sbl[tid] = bl[tid];

    const float4* lx4 = (const float4*)g_LX;
    const float4* lh4 = (const float4*)g_Lh;

    int ntiles = (N_NODES + 15) / 16;
    int warp = tid >> 5;
    int j = tid & 31;

    float* oh = out;
    float* oH = out + (size_t)N_NODES * HOR;
    float* oC = oH + (size_t)N_NODES * HID;

    for (int tile = blockIdx.x; tile < ntiles; tile += GBLOCKS) {
        int nodeBase = tile * 16;
        __syncthreads();
        for (int i = tid; i < 512; i += 256) {
            int n = i >> 5, m = (i >> 3) & 3, kq = i & 7;
            int node = nodeBase + n;
            float4 v = make_float4(0.f, 0.f, 0.f, 0.f);
            if (node < N_NODES) {
                if (m == 0) v = x4[node * 8 + kq];
                else if (m == 2) v = h04[node * 8 + kq];
                else {
                    v = (m == 1) ? lx4[node * 8 + kq] : lh4[node * 8 + kq];
                    float sc = -g_dinv[node];
                    v.x *= sc; v.y *= sc; v.z *= sc; v.w *= sc;
                }
            }
            ((float4*)sU)[(n * 4 + m) * 8 + kq] = v;
        }
        __syncthreads();

        float acc[2][4];
        #pragma unroll
        for (int n = 0; n < 2; n++)
            #pragma unroll
            for (int g = 0; g < 4; g++) acc[n][g] = 0.f;

        int nb = warp * 2;
        #pragma unroll
        for (int k = 0; k < 32; k++) {
            float wa[4], wb[4], wha[4], whb[4];
            #pragma unroll
            for (int g = 0; g < 4; g++) {
                wa[g]  = sWx[g * 2048 +        k * 32 + j];
                wb[g]  = sWx[g * 2048 + 1024 + k * 32 + j];
                wha[g] = __ldg(&Wh[g * 2048 +        k * 32 + j]);
                whb[g] = __ldg(&Wh[g * 2048 + 1024 + k * 32 + j]);
            }
            #pragma unroll
            for (int n = 0; n < 2; n++) {
                float xv  = sU[((nb + n) * 4 + 0) * 32 + k];
                float lxv = sU[((nb + n) * 4 + 1) * 32 + k];
                float hv  = sU[((nb + n) * 4 + 2) * 32 + k];
                float lhv = sU[((nb + n) * 4 + 3) * 32 + k];
                #pragma unroll
                for (int g = 0; g < 4; g++)
                    acc[n][g] += xv * wa[g] + lxv * wb[g] + hv * wha[g] + lhv * whb[g];
            }
        }

        #pragma unroll
        for (int n = 0; n < 2; n++) {
            int node = nodeBase + nb + n;
            if (node < N_NODES) {
                float c0v = c0[node * HID + j];
                float preI = acc[n][0] + sbsum[0 * 32 + j] + swc[0 * 32 + j] * c0v;
                float preF = acc[n][1] + sbsum[1 * 32 + j] + swc[1 * 32 + j] * c0v;
                float preT = acc[n][2] + sbsum[2 * 32 + j];
                float I  = 1.f / (1.f + __expf(-preI));
                float Fg = 1.f / (1.f + __expf(-preF));
                float T  = tanhf(preT);
                float C  = Fg * c0v + I * T;
                float preO = acc[n][3] + sbsum[3 * 32 + j] + swc[2 * 32 + j] * C;
                float O  = 1.f / (1.f + __expf(-preO));
                float H  = O * tanhf(C);

                oH[node * HID + j] = H;
                oC[node * HID + j] = C;

                float rH = fmaxf(H, 0.f);
                float keep = 0.f;
                #pragma unroll
                for (int k = 0; k < 32; k++) {
                    float rHk = __shfl_sync(0xffffffffu, rH, k);
                    if (j < HOR) keep += rHk * sWl[k * HOR + j];
                }
                if (j < HOR) oh[node * HOR + j] = keep + sbl[j];
            }
        }
    }
}

// ---------------- launch ----------------
extern "C" void kernel_launch(void* const* d_in, const int* in_sizes, int n_in,
                              void* d_out, int out_size) {
    int iX, iEI, iEW, iWx, iBx, iWh, iBh, iWc, iB, iWl, iBl, iH0, iC0;
    if (n_in > 8 && in_sizes[8] == 2 * N_EDGES) {
        iWl = 0; iWh = 1; iWx = 2; iB = 3; iBl = 4; iBh = 5; iBx = 6;
        iC0 = 7; iEI = 8; iEW = 9; iH0 = 10; iWc = 11; iX = 12;
    } else {
        iX = 0; iEI = 1; iEW = 2; iWx = 3; iBx = 4; iWh = 5; iBh = 6;
        iWc = 7; iB = 8; iWl = 9; iBl = 10; iH0 = 11; iC0 = 12;
    }

    const float* x    = (const float*)d_in[iX];
    const int*   ei   = (const int*)d_in[iEI];     // int32 (JAX x64 off)
    const float* ew   = (const float*)d_in[iEW];
    const float* Wx   = (const float*)d_in[iWx];
    const float* bx   = (const float*)d_in[iBx];
    const float* Wh   = (const float*)d_in[iWh];
    const float* bh   = (const float*)d_in[iBh];
    const float* wc   = (const float*)d_in[iWc];
    const float* b    = (const float*)d_in[iB];
    const float* Wl   = (const float*)d_in[iWl];
    const float* bl   = (const float*)d_in[iBl];
    const float* h0   = (const float*)d_in[iH0];
    const float* c0   = (const float*)d_in[iC0];
    float*       out  = (float*)d_out;

    const int* src = ei;
    const int* dst = ei + N_EDGES;

    void *pDeg, *pLX, *pLh, *pFlag;
    cudaGetSymbolAddress(&pDeg,  g_deg);
    cudaGetSymbolAddress(&pLX,   g_LX);
    cudaGetSymbolAddress(&pLh,   g_Lh);
    cudaGetSymbolAddress(&pFlag, g_hflag);
    cudaMemsetAsync(pDeg,  0, N_NODES * sizeof(float));
    cudaMemsetAsync(pLX,   0, N_NODES * HID * sizeof(float));
    cudaMemsetAsync(pLh,   0, N_NODES * HID * sizeof(float));
    cudaMemsetAsync(pFlag, 0, sizeof(int));

    k_deg<<<(N_NODES * HID / 4 + 255) / 256, 256>>>(
        (const int4*)src, (const float4*)ew, (const float4*)h0);

    k_xs<<<(N_NODES * 8 + 255) / 256, 256>>>(
        (const float4*)x, (const float4*)h0);

    long long warps = (N_EDGES + 31) / 32;
    k_edge<<<(int)((warps * 32 + 255) / 256), 256>>>(src, dst, ew);

    k_gates_fast<<<(N_NODES + TN - 1) / TN, 256>>>(
        (const float4*)x, c0, Wx, bx, bh, wc, b, Wl, bl, out);
    k_gates_hf<<<GBLOCKS, 256>>>(
        (const float4*)x, (const float4*)h0, c0,
        Wx, bx, Wh, bh, wc, b, Wl, bl, out);
}

// round 9
// speedup vs baseline: 1.0501x; 1.0446x over previous
#include <cuda_runtime.h>
#include <math.h>

#define N_NODES 50000
#define N_EDGES 1600000
#define HID 32
#define HOR 12

// ---------------- scratch (static device allocation) ----------------
__device__ float g_deg[N_NODES];
__device__ float g_dinv[N_NODES];
__device__ float4 g_Xs4[N_NODES * 8];    // dinv[s] * x[s]
__device__ float4 g_h0s4[N_NODES * 8];   // dinv[s] * h0[s]
__device__ float g_LX[N_NODES * HID];    // T = sum w * Xs   (scaled by -dinv[d] in gates)
__device__ float g_Lh[N_NODES * HID];
__device__ float g_WxT[4 * 2 * 32 * 32]; // transposed weights [g][m][j][k]
__device__ int   g_hflag;                // any(h0 != 0)

// ---------------- transpose Wx once: WT[g][m][j][k] = Wx[g][m][k][j] ----------------
__global__ void k_prep(const float* __restrict__ Wx) {
    int i = blockIdx.x * blockDim.x + threadIdx.x;   // 8192
    if (i < 8192) {
        int gm = i >> 10;          // 0..7
        int k  = (i >> 5) & 31;
        int j  = i & 31;
        g_WxT[(gm * 32 + j) * 32 + k] = Wx[(gm * 32 + k) * 32 + j];
    }
}

// ---------------- deg = segment_sum(w, src); fused h0!=0 probe; 4 edges/thread ----------------
__global__ void __launch_bounds__(256) k_deg(
        const int4* __restrict__ src4,
        const float4* __restrict__ w4,
        const float4* __restrict__ h04) {
    int i = blockIdx.x * blockDim.x + threadIdx.x;
    if (i < N_EDGES / 4) {
        int4   s = src4[i];
        float4 w = w4[i];
        if ((unsigned)s.x < N_NODES) atomicAdd(&g_deg[s.x], w.x);
        if ((unsigned)s.y < N_NODES) atomicAdd(&g_deg[s.y], w.y);
        if ((unsigned)s.z < N_NODES) atomicAdd(&g_deg[s.z], w.z);
        if ((unsigned)s.w < N_NODES) atomicAdd(&g_deg[s.w], w.w);
    }
    if (i < N_NODES * HID / 4) {
        float4 v = h04[i];
        if (v.x != 0.f || v.y != 0.f || v.z != 0.f || v.w != 0.f) g_hflag = 1;
    }
}

// ---------------- dinv + pre-scale Xs = dinv*x (and h0s if hf) ----------------
__global__ void __launch_bounds__(256) k_xs(
        const float4* __restrict__ x4,
        const float4* __restrict__ h04) {
    int i = blockIdx.x * blockDim.x + threadIdx.x;
    if (i < N_NODES * 8) {
        int node = i >> 3;
        float d = g_deg[node];
        float di = d > 0.f ? rsqrtf(d) : 0.f;
        if ((i & 7) == 0) g_dinv[node] = di;
        float4 v = x4[i];
        v.x *= di; v.y *= di; v.z *= di; v.w *= di;
        g_Xs4[i] = v;
        if (g_hflag) {
            float4 h = h04[i];
            h.x *= di; h.y *= di; h.z *= di; h.w *= di;
            g_h0s4[i] = h;
        }
    }
}

// ---------------- edge aggregation: T[dst] += w * Xs[src], vectorized RED.128 ----------------
__global__ void __launch_bounds__(256) k_edge(
        const int* __restrict__ src,
        const int* __restrict__ dst,
        const float* __restrict__ w) {
    int lane = threadIdx.x & 31;
    long long wid = (long long)(blockIdx.x * blockDim.x + threadIdx.x) >> 5;
    long long e = wid * 32 + lane;

    int s = 0, d = 0;
    float nv = 0.f;
    if (e < N_EDGES) {
        int ss = src[e];
        int dd = dst[e];
        if ((unsigned)ss < N_NODES && (unsigned)dd < N_NODES) {
            s = ss; d = dd; nv = w[e];
        }
    }
    int hf = g_hflag;
    int sub = lane >> 3;
    int q   = lane & 7;
    const float4* xs  = g_Xs4;
    const float4* h0s = g_h0s4;

    #pragma unroll
    for (int it = 0; it < 8; it++) {
        int srcLane = it * 4 + sub;
        int   si  = __shfl_sync(0xffffffffu, s, srcLane);
        int   di  = __shfl_sync(0xffffffffu, d, srcLane);
        float nvi = __shfl_sync(0xffffffffu, nv, srcLane);
        if (nvi != 0.f) {
            float4 xv = __ldg(&xs[(size_t)si * 8 + q]);
            asm volatile("red.global.add.v4.f32 [%0], {%1,%2,%3,%4};"
                         :: "l"(&g_LX[di * HID + q * 4]),
                            "f"(nvi * xv.x), "f"(nvi * xv.y),
                            "f"(nvi * xv.z), "f"(nvi * xv.w)
                         : "memory");
            if (hf) {
                float4 hv = __ldg(&h0s[(size_t)si * 8 + q]);
                asm volatile("red.global.add.v4.f32 [%0], {%1,%2,%3,%4};"
                             :: "l"(&g_Lh[di * HID + q * 4]),
                                "f"(nvi * hv.x), "f"(nvi * hv.y),
                                "f"(nvi * hv.z), "f"(nvi * hv.w)
                             : "memory");
            }
        }
    }
}

// helpers for packed f32x2
__device__ __forceinline__ unsigned long long ffma2(
        unsigned long long a, unsigned long long bb, unsigned long long c) {
    unsigned long long r;
    asm("fma.rn.f32x2 %0, %1, %2, %3;" : "=l"(r) : "l"(a), "l"(bb), "l"(c));
    return r;
}
__device__ __forceinline__ float fold2(unsigned long long a) {
    float lo = __uint_as_float((unsigned)(a & 0xffffffffu));
    float hi = __uint_as_float((unsigned)(a >> 32));
    return lo + hi;
}

// ================= FAST gates kernel (h0 == 0): f32x2 k-paired mainloop =================
// 32 nodes/block, 4 per warp. smem ~45.5 KB.
#define TN 32
#define WPITCH 34   // floats per [g][m][j] row (pad 2 -> 2-way LDS.64 conflict only)
__global__ void __launch_bounds__(256) k_gates_fast(
        const float4* __restrict__ x4,
        const float* __restrict__ c0,
        const float* __restrict__ bx,
        const float* __restrict__ bh,
        const float* __restrict__ wc,
        const float* __restrict__ b,
        const float* __restrict__ Wl,   // [32][12]
        const float* __restrict__ bl,
        float* __restrict__ out) {
    if (g_hflag) return;

    __shared__ float sWt[256 * WPITCH];   // 8 mats * 32 j rows, pitch 34 = 34816 B
    __shared__ float sU[TN * 64];         // 8 KB  [node][m*32+k]
    __shared__ float sWl[HID * HOR];
    __shared__ float sbsum[4 * HID];
    __shared__ float swc[3 * HID];
    __shared__ float sbl[HOR];

    int tid = threadIdx.x;
    int nodeBase = blockIdx.x * TN;

    // stage transposed weights: row = gm*32+j (256 rows), 32 k each
    for (int i = tid; i < 8192; i += 256) {
        int row = i >> 5, k = i & 31;
        sWt[row * WPITCH + k] = g_WxT[i];
    }
    for (int i = tid; i < HID * HOR; i += 256) sWl[i] = Wl[i];
    if (tid < 4 * HID) sbsum[tid] = bx[tid] + bh[tid] + b[tid];
    if (tid < 3 * HID) swc[tid] = wc[tid];
    if (tid < HOR)     sbl[tid] = bl[tid];

    const float4* lx4 = (const float4*)g_LX;

    // stage U: [node][0..31]=x, [node][32..63]=-dinv*T
    for (int i = tid; i < TN * 16; i += 256) {
        int n = i >> 4, m = (i >> 3) & 1, kq = i & 7;
        int node = nodeBase + n;
        float4 v = make_float4(0.f, 0.f, 0.f, 0.f);
        if (node < N_NODES) {
            if (m) {
                v = lx4[node * 8 + kq];
                float sc = -g_dinv[node];
                v.x *= sc; v.y *= sc; v.z *= sc; v.w *= sc;
            } else {
                v = x4[node * 8 + kq];
            }
        }
        ((float4*)sU)[(n * 2 + m) * 8 + kq] = v;
    }
    __syncthreads();

    int warp = tid >> 5;
    int j = tid & 31;
    int nb = warp * 4;

    // packed accumulators: acc2[node][gate], halves hold k-even / k-odd partials
    unsigned long long acc2[4][4];
    #pragma unroll
    for (int n = 0; n < 4; n++)
        #pragma unroll
        for (int g = 0; g < 4; g++) acc2[n][g] = 0ull;

    #pragma unroll
    for (int kk = 0; kk < 16; kk++) {       // k = 2*kk
        unsigned long long wa[4], wb[4];
        #pragma unroll
        for (int g = 0; g < 4; g++) {
            // rows: gm = g*2 + m ; row index = gm*32 + j
            wa[g] = *(const unsigned long long*)&sWt[((g * 2 + 0) * 32 + j) * WPITCH + 2 * kk];
            wb[g] = *(const unsigned long long*)&sWt[((g * 2 + 1) * 32 + j) * WPITCH + 2 * kk];
        }
        #pragma unroll
        for (int n = 0; n < 4; n++) {
            unsigned long long u0 = *(const unsigned long long*)&sU[(nb + n) * 64 + 2 * kk];       // {x[k],x[k+1]}
            unsigned long long u1 = *(const unsigned long long*)&sU[(nb + n) * 64 + 32 + 2 * kk];  // {lx[k],lx[k+1]}
            #pragma unroll
            for (int g = 0; g < 4; g++) {
                acc2[n][g] = ffma2(u0, wa[g], acc2[n][g]);
                acc2[n][g] = ffma2(u1, wb[g], acc2[n][g]);
            }
        }
    }

    float* oh = out;
    float* oH = out + (size_t)N_NODES * HOR;
    float* oC = oH + (size_t)N_NODES * HID;

    #pragma unroll
    for (int n = 0; n < 4; n++) {
        int node = nodeBase + nb + n;
        if (node < N_NODES) {
            float a0 = fold2(acc2[n][0]);
            float a1 = fold2(acc2[n][1]);
            float a2 = fold2(acc2[n][2]);
            float a3 = fold2(acc2[n][3]);
            float c0v = c0[node * HID + j];
            float preI = a0 + sbsum[0 * 32 + j] + swc[0 * 32 + j] * c0v;
            float preF = a1 + sbsum[1 * 32 + j] + swc[1 * 32 + j] * c0v;
            float preT = a2 + sbsum[2 * 32 + j];
            float I  = 1.f / (1.f + __expf(-preI));
            float Fg = 1.f / (1.f + __expf(-preF));
            float T  = tanhf(preT);
            float C  = Fg * c0v + I * T;
            float preO = a3 + sbsum[3 * 32 + j] + swc[2 * 32 + j] * C;
            float O  = 1.f / (1.f + __expf(-preO));
            float H  = O * tanhf(C);

            oH[node * HID + j] = H;
            oC[node * HID + j] = C;

            float rH = fmaxf(H, 0.f);
            float keep = 0.f;
            #pragma unroll
            for (int k = 0; k < 32; k++) {
                float rHk = __shfl_sync(0xffffffffu, rH, k);
                if (j < HOR) keep += rHk * sWl[k * HOR + j];
            }
            if (j < HOR) oh[node * HOR + j] = keep + sbl[j];
        }
    }
}

// ================= GENERIC gates kernel: only runs when h0 != 0 =================
#define GBLOCKS 592
__global__ void __launch_bounds__(256) k_gates_hf(
        const float4* __restrict__ x4,
        const float4* __restrict__ h04,
        const float* __restrict__ c0,
        const float* __restrict__ Wx,
        const float* __restrict__ bx,
        const float* __restrict__ Wh,
        const float* __restrict__ bh,
        const float* __restrict__ wc,
        const float* __restrict__ b,
        const float* __restrict__ Wl,
        const float* __restrict__ bl,
        float* __restrict__ out) {
    if (!g_hflag) return;

    __shared__ float sWx[8192];
    __shared__ float sU[16 * 4 * 32];
    __shared__ float sWl[HID * HOR];
    __shared__ float sbsum[4 * HID];
    __shared__ float swc[3 * HID];
    __shared__ float sbl[HOR];

    int tid = threadIdx.x;

    for (int i = tid; i < 8192; i += 256) sWx[i] = Wx[i];
    for (int i = tid; i < HID * HOR; i += 256) sWl[i] = Wl[i];
    if (tid < 4 * HID) sbsum[tid] = bx[tid] + bh[tid] + b[tid];
    if (tid < 3 * HID) swc[tid] = wc[tid];
    if (tid < HOR)     sbl[tid] = bl[tid];

    const float4* lx4 = (const float4*)g_LX;
    const float4* lh4 = (const float4*)g_Lh;

    int ntiles = (N_NODES + 15) / 16;
    int warp = tid >> 5;
    int j = tid & 31;

    float* oh = out;
    float* oH = out + (size_t)N_NODES * HOR;
    float* oC = oH + (size_t)N_NODES * HID;

    for (int tile = blockIdx.x; tile < ntiles; tile += GBLOCKS) {
        int nodeBase = tile * 16;
        __syncthreads();
        for (int i = tid; i < 512; i += 256) {
            int n = i >> 5, m = (i >> 3) & 3, kq = i & 7;
            int node = nodeBase + n;
            float4 v = make_float4(0.f, 0.f, 0.f, 0.f);
            if (node < N_NODES) {
                if (m == 0) v = x4[node * 8 + kq];
                else if (m == 2) v = h04[node * 8 + kq];
                else {
                    v = (m == 1) ? lx4[node * 8 + kq] : lh4[node * 8 + kq];
                    float sc = -g_dinv[node];
                    v.x *= sc; v.y *= sc; v.z *= sc; v.w *= sc;
                }
            }
            ((float4*)sU)[(n * 4 + m) * 8 + kq] = v;
        }
        __syncthreads();

        float acc[2][4];
        #pragma unroll
        for (int n = 0; n < 2; n++)
            #pragma unroll
            for (int g = 0; g < 4; g++) acc[n][g] = 0.f;

        int nb = warp * 2;
        #pragma unroll
        for (int k = 0; k < 32; k++) {
            float wa[4], wb[4], wha[4], whb[4];
            #pragma unroll
            for (int g = 0; g < 4; g++) {
                wa[g]  = sWx[g * 2048 +        k * 32 + j];
                wb[g]  = sWx[g * 2048 + 1024 + k * 32 + j];
                wha[g] = __ldg(&Wh[g * 2048 +        k * 32 + j]);
                whb[g] = __ldg(&Wh[g * 2048 + 1024 + k * 32 + j]);
            }
            #pragma unroll
            for (int n = 0; n < 2; n++) {
                float xv  = sU[((nb + n) * 4 + 0) * 32 + k];
                float lxv = sU[((nb + n) * 4 + 1) * 32 + k];
                float hv  = sU[((nb + n) * 4 + 2) * 32 + k];
                float lhv = sU[((nb + n) * 4 + 3) * 32 + k];
                #pragma unroll
                for (int g = 0; g < 4; g++)
                    acc[n][g] += xv * wa[g] + lxv * wb[g] + hv * wha[g] + lhv * whb[g];
            }
        }

        #pragma unroll
        for (int n = 0; n < 2; n++) {
            int node = nodeBase + nb + n;
            if (node < N_NODES) {
                float c0v = c0[node * HID + j];
                float preI = acc[n][0] + sbsum[0 * 32 + j] + swc[0 * 32 + j] * c0v;
                float preF = acc[n][1] + sbsum[1 * 32 + j] + swc[1 * 32 + j] * c0v;
                float preT = acc[n][2] + sbsum[2 * 32 + j];
                float I  = 1.f / (1.f + __expf(-preI));
                float Fg = 1.f / (1.f + __expf(-preF));
                float T  = tanhf(preT);
                float C  = Fg * c0v + I * T;
                float preO = acc[n][3] + sbsum[3 * 32 + j] + swc[2 * 32 + j] * C;
                float O  = 1.f / (1.f + __expf(-preO));
                float H  = O * tanhf(C);

                oH[node * HID + j] = H;
                oC[node * HID + j] = C;

                float rH = fmaxf(H, 0.f);
                float keep = 0.f;
                #pragma unroll
                for (int k = 0; k < 32; k++) {
                    float rHk = __shfl_sync(0xffffffffu, rH, k);
                    if (j < HOR) keep += rHk * sWl[k * HOR + j];
                }
                if (j < HOR) oh[node * HOR + j] = keep + sbl[j];
            }
        }
    }
}

// ---------------- launch ----------------
extern "C" void kernel_launch(void* const* d_in, const int* in_sizes, int n_in,
                              void* d_out, int out_size) {
    int iX, iEI, iEW, iWx, iBx, iWh, iBh, iWc, iB, iWl, iBl, iH0, iC0;
    if (n_in > 8 && in_sizes[8] == 2 * N_EDGES) {
        iWl = 0; iWh = 1; iWx = 2; iB = 3; iBl = 4; iBh = 5; iBx = 6;
        iC0 = 7; iEI = 8; iEW = 9; iH0 = 10; iWc = 11; iX = 12;
    } else {
        iX = 0; iEI = 1; iEW = 2; iWx = 3; iBx = 4; iWh = 5; iBh = 6;
        iWc = 7; iB = 8; iWl = 9; iBl = 10; iH0 = 11; iC0 = 12;
    }

    const float* x    = (const float*)d_in[iX];
    const int*   ei   = (const int*)d_in[iEI];     // int32 (JAX x64 off)
    const float* ew   = (const float*)d_in[iEW];
    const float* Wx   = (const float*)d_in[iWx];
    const float* bx   = (const float*)d_in[iBx];
    const float* Wh   = (const float*)d_in[iWh];
    const float* bh   = (const float*)d_in[iBh];
    const float* wc   = (const float*)d_in[iWc];
    const float* b    = (const float*)d_in[iB];
    const float* Wl   = (const float*)d_in[iWl];
    const float* bl   = (const float*)d_in[iBl];
    const float* h0   = (const float*)d_in[iH0];
    const float* c0   = (const float*)d_in[iC0];
    float*       out  = (float*)d_out;

    const int* src = ei;
    const int* dst = ei + N_EDGES;

    void *pDeg, *pLX, *pLh, *pFlag;
    cudaGetSymbolAddress(&pDeg,  g_deg);
    cudaGetSymbolAddress(&pLX,   g_LX);
    cudaGetSymbolAddress(&pLh,   g_Lh);
    cudaGetSymbolAddress(&pFlag, g_hflag);
    cudaMemsetAsync(pDeg,  0, N_NODES * sizeof(float));
    cudaMemsetAsync(pLX,   0, N_NODES * HID * sizeof(float));
    cudaMemsetAsync(pLh,   0, N_NODES * HID * sizeof(float));
    cudaMemsetAsync(pFlag, 0, sizeof(int));

    k_prep<<<32, 256>>>(Wx);

    k_deg<<<(N_NODES * HID / 4 + 255) / 256, 256>>>(
        (const int4*)src, (const float4*)ew, (const float4*)h0);

    k_xs<<<(N_NODES * 8 + 255) / 256, 256>>>(
        (const float4*)x, (const float4*)h0);

    long long warps = (N_EDGES + 31) / 32;
    k_edge<<<(int)((warps * 32 + 255) / 256), 256>>>(src, dst, ew);

    k_gates_fast<<<(N_NODES + TN - 1) / TN, 256>>>(
        (const float4*)x, c0, bx, bh, wc, b, Wl, bl, out);
    k_gates_hf<<<GBLOCKS, 256>>>(
        (const float4*)x, (const float4*)h0, c0,
        Wx, bx, Wh, bh, wc, b, Wl, bl, out);
}